// round 13
// baseline (speedup 1.0000x reference)
#include <cuda_runtime.h>
#include <math.h>

// Problem constants
#define B_    64
#define T_    1024
#define DIN_  512
#define H_    2048
#define DOUT_ 512
#define FH_   8192     // 4*H
#define NCTA  128
#define NTHR  512

typedef unsigned long long u64;

// ---------------- static device scratch (no allocation allowed) ----------------
__device__ float g_h[2][B_ * H_];            // ping-pong hidden state
__device__ float g_y[B_ * DOUT_];            // previous prediction y_{t-1}
__device__ float g_ypart[16][B_ * DOUT_];    // split-K partials for y projection
__device__ unsigned g_bar_count = 0;         // grid barrier arrival counter
__device__ volatile unsigned g_bar_gen = 0;  // grid barrier generation (monotonic)

// ---------------- packed f32x2 helpers (ptxas will not auto-fuse) --------------
__device__ __forceinline__ u64 ffma2(u64 a, u64 b, u64 c) {
    u64 d;
    asm("fma.rn.f32x2 %0, %1, %2, %3;" : "=l"(d) : "l"(a), "l"(b), "l"(c));
    return d;
}
__device__ __forceinline__ u64 dup2(float x) {
    u64 d;
    asm("mov.b64 %0, {%1, %1};" : "=l"(d) : "f"(x));
    return d;
}
__device__ __forceinline__ float sgm(float v) { return 1.0f / (1.0f + expf(-v)); }

// ---------------- software grid barrier (all 128 CTAs resident) ----------------
__device__ __forceinline__ void gridbar(unsigned target) {
    __syncthreads();
    if (threadIdx.x == 0) {
        __threadfence();
        if (atomicAdd(&g_bar_count, 1u) == NCTA - 1u) {
            g_bar_count = 0u;
            __threadfence();
            g_bar_gen = target;
        } else {
            while ((int)(g_bar_gen - target) < 0) { }
        }
        __threadfence();
    }
    __syncthreads();
}

// ---------------- gate GEMM operand source per K-chunk ----------------
// Global reduction index kg in [0,3072): [0,512)=x_t (Wi rows), [512,1024)=y_prev
// (Wi rows), [1024,3072)=h_prev (Wh rows). Chunk width 32 divides the boundaries.
__device__ __forceinline__ void chunk_src(
    int k0, int t, const float* __restrict__ x, const float* __restrict__ Wi,
    const float* __restrict__ Wh, const float* __restrict__ yprev,
    const float* __restrict__ hprev,
    const float*& Ab, size_t& strA, const float*& Wb)
{
    if (k0 < 512) {
        Ab = x + (size_t)t * DIN_ + (size_t)k0;   // x[m][t][k], row stride T*DIN
        strA = (size_t)T_ * DIN_;
        Wb = Wi + (size_t)k0 * FH_;
    } else if (k0 < 1024) {
        Ab = yprev + (k0 - 512);
        strA = DOUT_;
        Wb = Wi + (size_t)k0 * FH_;
    } else {
        Ab = hprev + (k0 - 1024);
        strA = H_;
        Wb = Wh + (size_t)(k0 - 1024) * FH_;
    }
}

// ======================= single persistent kernel =======================
// 128 CTAs x 512 threads. CTA bx owns hidden units u0=16*bx..u0+15 (all 64 batch
// rows): its 64x64 z tile columns are [i|f|g|o] x 16 units (smem col j maps to
// weight column (j>>4)*2048 + u0 + (j&15)), enabling a fully fused LSTM epilogue
// with CTA-private c state. Per step: gates GEMM+pointwise | bar | y-proj
// split-K(16)xN(8) | bar | y-reduce | bar.
__global__ void __launch_bounds__(NTHR, 1) k_lstm_persistent(
    const float* __restrict__ x,  const float* __restrict__ c0,
    const float* __restrict__ h0, const float* __restrict__ y0,
    const float* __restrict__ Wi, const float* __restrict__ Wh,
    const float* __restrict__ bias, const float* __restrict__ Wo,
    const float* __restrict__ bo,
    float* __restrict__ out_c, float* __restrict__ out_h,
    float* __restrict__ out_y, float* __restrict__ out_ys)
{
    __shared__ __align__(16) float sm[8704];  // 2x As[32][68] + 2x Bs[32][68]; z aliases

    const int tid = threadIdx.x;
    const int bx  = blockIdx.x;
    const int u0  = bx * 16;

    // loader mappings (one float4 per thread per tile)
    const int am = tid & 63, ak = (tid >> 6) * 4;          // A: row am, k-off ak
    const int bk = tid >> 4, bc = (tid & 15) * 4;          // B: row bk, smem col bc
    const int bcolG = (bc >> 4) * 2048 + u0 + (bc & 15);   // gate-interleaved col
    // compute mapping: thread tile 2m x 4n
    const int tx = tid & 15, ty = tid >> 4;
    const int m0 = ty * 2, n0 = tx * 4;

    unsigned bar = g_bar_gen;   // persisted base generation (stable: no writers now)

    // ---------------- init: states ----------------
    {
        // CTA-private c and h slices (owner mapping keeps c resident on this SM)
#pragma unroll
        for (int r = 0; r < 2; r++) {
            int cell = tid + NTHR * r;            // 0..1023
            int mm = cell >> 4, up = cell & 15;
            size_t gi = (size_t)mm * H_ + u0 + up;
            out_c[gi]  = c0[gi];
            g_h[0][gi] = h0[gi];
        }
        int yi = bx * 256 + (tid & 255);
        if (tid < 256) g_y[yi] = y0[yi];
    }
    gridbar(++bar);

    // ---------------- time loop ----------------
    for (int t = 0; t < T_; t++) {
        const int pp = t & 1;
        const float* __restrict__ yprev = g_y;
        const float* __restrict__ hprev = g_h[pp];
        float* __restrict__ hnext       = g_h[pp ^ 1];

        // ===== gates GEMM: 96 chunks of K=32, double-buffered =====
        u64 acc[2][2];
        acc[0][0] = acc[0][1] = acc[1][0] = acc[1][1] = 0ull;

        {   // preload chunk 0
            const float *Ab, *Wb; size_t strA;
            chunk_src(0, t, x, Wi, Wh, yprev, hprev, Ab, strA, Wb);
            float4 a4 = __ldcg((const float4*)(Ab + (size_t)am * strA + ak));
            float4 b4 = __ldg ((const float4*)(Wb + (size_t)bk * FH_ + bcolG));
            sm[(ak + 0) * 68 + am] = a4.x;
            sm[(ak + 1) * 68 + am] = a4.y;
            sm[(ak + 2) * 68 + am] = a4.z;
            sm[(ak + 3) * 68 + am] = a4.w;
            *(float4*)&sm[4352 + bk * 68 + bc] = b4;
        }
        __syncthreads();

        for (int c = 0; c < 96; c++) {
            const int cur = c & 1;
            const bool hn = (c + 1 < 96);
            float4 a4, b4;
            if (hn) {
                const float *Ab, *Wb; size_t strA;
                chunk_src((c + 1) * 32, t, x, Wi, Wh, yprev, hprev, Ab, strA, Wb);
                a4 = __ldcg((const float4*)(Ab + (size_t)am * strA + ak));
                b4 = __ldg ((const float4*)(Wb + (size_t)bk * FH_ + bcolG));
            }
            const float* As = &sm[cur * 2176];
            const float* Bs = &sm[4352 + cur * 2176];
#pragma unroll
            for (int kk = 0; kk < 32; kk++) {
                float2 av = *(const float2*)&As[kk * 68 + m0];
                ulonglong2 bv = *(const ulonglong2*)&Bs[kk * 68 + n0];
                u64 a0 = dup2(av.x), a1 = dup2(av.y);
                acc[0][0] = ffma2(a0, bv.x, acc[0][0]);
                acc[0][1] = ffma2(a0, bv.y, acc[0][1]);
                acc[1][0] = ffma2(a1, bv.x, acc[1][0]);
                acc[1][1] = ffma2(a1, bv.y, acc[1][1]);
            }
            if (hn) {
                const int nb2 = cur ^ 1;
                float* Aw = &sm[nb2 * 2176];
                Aw[(ak + 0) * 68 + am] = a4.x;
                Aw[(ak + 1) * 68 + am] = a4.y;
                Aw[(ak + 2) * 68 + am] = a4.z;
                Aw[(ak + 3) * 68 + am] = a4.w;
                *(float4*)&sm[4352 + nb2 * 2176 + bk * 68 + bc] = b4;
            }
            __syncthreads();
        }

        // ===== stage z through smem; fused LSTM pointwise =====
        {
            float* zz = sm;   // z[m][68] aliases GEMM buffers (loop ended on a sync)
            *(u64*)&zz[(m0 + 0) * 68 + n0]     = acc[0][0];
            *(u64*)&zz[(m0 + 0) * 68 + n0 + 2] = acc[0][1];
            *(u64*)&zz[(m0 + 1) * 68 + n0]     = acc[1][0];
            *(u64*)&zz[(m0 + 1) * 68 + n0 + 2] = acc[1][1];
            __syncthreads();
#pragma unroll
            for (int r = 0; r < 2; r++) {
                int cell = tid + NTHR * r;        // 0..1023
                int mm = cell >> 4, up = cell & 15;
                float zi = zz[mm * 68 + up]      + bias[u0 + up];
                float zf = zz[mm * 68 + 16 + up] + bias[2048 + u0 + up];
                float zg = zz[mm * 68 + 32 + up] + bias[4096 + u0 + up];
                float zo = zz[mm * 68 + 48 + up] + bias[6144 + u0 + up];
                size_t gi = (size_t)mm * H_ + u0 + up;
                float cold = out_c[gi];           // CTA-private: L1-resident
                float nc = sgm(zf) * cold + sgm(zi) * tanhf(zg);
                float nh = sgm(zo) * tanhf(nc);
                out_c[gi] = nc;
                hnext[gi] = nh;
            }
        }
        gridbar(++bar);   // h_t published

        // ===== y projection: split K(16 x 128) x N(8 x 64) =====
        {
            const int nb = bx & 7, ks = bx >> 3;
            const int kbase = ks * 128;
            const float* __restrict__ h = g_h[pp ^ 1];
            u64 ya[2][2];
            ya[0][0] = ya[0][1] = ya[1][0] = ya[1][1] = 0ull;
            for (int c = 0; c < 4; c++) {
                int k0 = kbase + c * 32;
                float4 a4 = __ldcg((const float4*)(h + (size_t)am * H_ + k0 + ak));
                float4 b4 = __ldg ((const float4*)(Wo + (size_t)(k0 + bk) * DOUT_ + nb * 64 + bc));
                __syncthreads();   // protect smem reuse across iterations
                sm[(ak + 0) * 68 + am] = a4.x;
                sm[(ak + 1) * 68 + am] = a4.y;
                sm[(ak + 2) * 68 + am] = a4.z;
                sm[(ak + 3) * 68 + am] = a4.w;
                *(float4*)&sm[4352 + bk * 68 + bc] = b4;
                __syncthreads();
#pragma unroll
                for (int kk = 0; kk < 32; kk++) {
                    float2 av = *(const float2*)&sm[kk * 68 + m0];
                    ulonglong2 bv = *(const ulonglong2*)&sm[4352 + kk * 68 + n0];
                    u64 a0 = dup2(av.x), a1 = dup2(av.y);
                    ya[0][0] = ffma2(a0, bv.x, ya[0][0]);
                    ya[0][1] = ffma2(a0, bv.y, ya[0][1]);
                    ya[1][0] = ffma2(a1, bv.x, ya[1][0]);
                    ya[1][1] = ffma2(a1, bv.y, ya[1][1]);
                }
            }
            float* dst0 = &g_ypart[ks][(size_t)(m0 + 0) * DOUT_ + nb * 64 + n0];
            float* dst1 = &g_ypart[ks][(size_t)(m0 + 1) * DOUT_ + nb * 64 + n0];
            *(u64*)dst0 = ya[0][0]; *(u64*)(dst0 + 2) = ya[0][1];
            *(u64*)dst1 = ya[1][0]; *(u64*)(dst1 + 2) = ya[1][1];
        }
        gridbar(++bar);   // partials published

        // ===== y reduce: 256 outputs per CTA =====
        if (tid < 256) {
            int o = bx * 256 + tid;               // 0..32767
            float s = __ldg(&bo[o & 511]);
#pragma unroll
            for (int ks = 0; ks < 16; ks++) s += __ldcg(&g_ypart[ks][o]);
            g_y[o] = s;
            int mm = o >> 9, cN = o & 511;
            out_ys[(size_t)mm * ((size_t)T_ * DOUT_) + (size_t)t * DOUT_ + cN] = s;
        }
        gridbar(++bar);   // y_t published
    }

    // ---------------- final: h_f, y_f ----------------
    {
        int idx = bx * NTHR + tid;                // 0..65535
        out_h[idx]         = __ldcg(&g_h[0][idx]);           // T even -> final h in buf 0
        out_h[idx + 65536] = __ldcg(&g_h[0][idx + 65536]);
        if (idx < B_ * DOUT_) out_y[idx] = __ldcg(&g_y[idx]);
    }
}

// ---------------- host launcher: ONE graph node ----------------
extern "C" void kernel_launch(void* const* d_in, const int* in_sizes, int n_in,
                              void* d_out, int out_size) {
    (void)in_sizes; (void)n_in; (void)out_size;
    const float* x  = (const float*)d_in[0];
    const float* c0 = (const float*)d_in[1];
    const float* h0 = (const float*)d_in[2];
    const float* y0 = (const float*)d_in[3];
    const float* Wi = (const float*)d_in[4];
    const float* Wh = (const float*)d_in[5];
    const float* b  = (const float*)d_in[6];
    const float* Wo = (const float*)d_in[7];
    const float* bo = (const float*)d_in[8];

    // Output layout: c_f [64,2048] | h_f [64,2048] | y_f [64,512] | ys [64,1024,512]
    float* out    = (float*)d_out;
    float* out_c  = out;
    float* out_h  = out + 131072;
    float* out_y  = out + 262144;
    float* out_ys = out + 294912;

    k_lstm_persistent<<<NCTA, NTHR>>>(x, c0, h0, y0, Wi, Wh, b, Wo, bo,
                                      out_c, out_h, out_y, out_ys);
}